// round 2
// baseline (speedup 1.0000x reference)
#include <cuda_runtime.h>
#include <math_constants.h>

// Problem constants (from reference): img (1,200,200,512) f32 NHWC,
// rois (1,128,4) f32 (x,y,w,h), pool 7x7 -> out (1,128,7,7,512) f32.
#define IMG_H 200
#define IMG_W 200
#define IMG_C 512
#define POOLP 7
#define NROIS 128

// One CTA per (roi, jy, ix) bin. 128 threads, each owns 4 channels (float4).
// Channels are innermost/contiguous: each pixel's 512 ch = 2048 B = one fully
// coalesced 128-thread float4 load.
__global__ __launch_bounds__(128) void roi_pool_kernel(
    const float* __restrict__ img,
    const float* __restrict__ rois,
    float4* __restrict__ out)
{
    const int bin = blockIdx.x % (POOLP * POOLP);
    const int roi = blockIdx.x / (POOLP * POOLP);
    const int jy = bin / POOLP;
    const int ix = bin % POOLP;
    const int tid = threadIdx.x;

    // ROI params
    const float rx = rois[roi * 4 + 0];
    const float ry = rois[roi * 4 + 1];
    const float rw = rois[roi * 4 + 2];
    const float rh = rois[roi * 4 + 3];

    // Bin boundaries, matching JAX f32 op order exactly:
    //   step = w / 7 ; b[k] = int(x + k*step)   (mul then add, NO fma fusion)
    const float stepx = __fdiv_rn(rw, 7.0f);
    const float stepy = __fdiv_rn(rh, 7.0f);
    int bx0 = (int)__fadd_rn(rx, __fmul_rn((float)ix, stepx));
    int bx1 = (int)__fadd_rn(rx, __fmul_rn((float)(ix + 1), stepx));
    int by0 = (int)__fadd_rn(ry, __fmul_rn((float)jy, stepy));
    int by1 = (int)__fadd_rn(ry, __fmul_rn((float)(jy + 1), stepy));

    // Reference guarantees in-bounds, but clamp defensively (no perf cost).
    bx0 = max(bx0, 0); by0 = max(by0, 0);
    bx1 = min(bx1, IMG_W); by1 = min(by1, IMG_H);

    const float4* __restrict__ img4 = (const float4*)img;

    // Two independent accumulators to break the serial fmax chain and let the
    // compiler batch loads (MLP) against L2 latency.
    float4 m0 = make_float4(-CUDART_INF_F, -CUDART_INF_F, -CUDART_INF_F, -CUDART_INF_F);
    float4 m1 = m0;

    for (int row = by0; row < by1; ++row) {
        // base index (in float4 units) of this pixel row segment
        long base = ((long)row * IMG_W + bx0) * (IMG_C / 4) + tid;
        int ncol = bx1 - bx0;
        int col = 0;
        #pragma unroll 2
        for (; col + 1 < ncol; col += 2) {
            float4 v0 = __ldg(&img4[base + (long)col * (IMG_C / 4)]);
            float4 v1 = __ldg(&img4[base + (long)(col + 1) * (IMG_C / 4)]);
            m0.x = fmaxf(m0.x, v0.x); m0.y = fmaxf(m0.y, v0.y);
            m0.z = fmaxf(m0.z, v0.z); m0.w = fmaxf(m0.w, v0.w);
            m1.x = fmaxf(m1.x, v1.x); m1.y = fmaxf(m1.y, v1.y);
            m1.z = fmaxf(m1.z, v1.z); m1.w = fmaxf(m1.w, v1.w);
        }
        if (col < ncol) {
            float4 v0 = __ldg(&img4[base + (long)col * (IMG_C / 4)]);
            m0.x = fmaxf(m0.x, v0.x); m0.y = fmaxf(m0.y, v0.y);
            m0.z = fmaxf(m0.z, v0.z); m0.w = fmaxf(m0.w, v0.w);
        }
    }

    float4 m;
    m.x = fmaxf(m0.x, m1.x);
    m.y = fmaxf(m0.y, m1.y);
    m.z = fmaxf(m0.z, m1.z);
    m.w = fmaxf(m0.w, m1.w);

    // out[roi][jy][ix][c] ; 512 ch = 128 float4 per bin
    out[(size_t)blockIdx.x * (IMG_C / 4) + tid] = m;
}

extern "C" void kernel_launch(void* const* d_in, const int* in_sizes, int n_in,
                              void* d_out, int out_size)
{
    const float* img  = (const float*)d_in[0];
    const float* rois = (const float*)d_in[1];
    // d_in[2] = pool_size (always 7; shapes are compile-time constants here)
    float4* out = (float4*)d_out;

    dim3 grid(NROIS * POOLP * POOLP);  // 6272 CTAs
    roi_pool_kernel<<<grid, 128>>>(img, rois, out);
}